// round 3
// baseline (speedup 1.0000x reference)
#include <cuda_runtime.h>
#include <cstdint>

// FP4RoundingPerturb — output layout (float32, flattened concat):
//   [0,      N)           y
//   [N,      2N)          codes (as float)
//   [2N,     2N+B)        scales (e8m0+127 as float), B=N/32
//   [2N+B,   2N+B+7)      shifted_bounds
//   [2N+B+7, 2N+B+7+8N)   weights   <-- base float offset ≡ 3 (mod 4)

#define WARPS_PER_CTA 8
#define STEPS 4
// One warp handles 128 consecutive elements in 4 steps of 32.
// Each step, lane L owns element 32c+L; the 32-elem step IS one amax block.

__device__ float g_sb[8];   // shifted bounds
__device__ float g_K[8];    // exp(sb / tau)

__global__ void prep_kernel(const float* __restrict__ delta_raw,
                            const float* __restrict__ bounds_base,
                            float* __restrict__ sb_out) {
    int i = threadIdx.x;
    if (i < 7) {
        float shift = 0.5f * tanhf(delta_raw[0]);
        float sb = bounds_base[i] + shift;
        g_sb[i] = sb;
        g_K[i] = __expf(sb * 10.0f);
        sb_out[i] = sb;
    }
}

// 1-bit XOR swizzle on float4 slots: conflict-free for writer (stride-32B
// STS.128, slots 2L / 2L+1) AND reader (stride-16B LDS.128, consecutive slots).
__device__ __forceinline__ int swz(int s) { return s ^ ((s >> 3) & 1); }

__global__ void __launch_bounds__(32 * WARPS_PER_CTA)
fp4_main(const float* __restrict__ x,
         const float* __restrict__ values_table,
         float* __restrict__ y,
         float* __restrict__ codes,
         float* __restrict__ scales,
         float* __restrict__ weights,   // float offset ≡ 3 (mod 4)
         int n_elems) {
    // per-warp staging: 64 float4 slots = 1KB
    __shared__ float4 s_w[WARPS_PER_CTA][64];

    int tid  = threadIdx.x;
    int warp = tid >> 5;
    int lane = tid & 31;
    int base = (blockIdx.x * WARPS_PER_CTA + warp) * (32 * STEPS);
    if (base >= n_elems) return;

    float vt_reg = values_table[lane & 7];   // table lookup via shfl
    float sb0 = g_sb[0], sb1 = g_sb[1], sb2 = g_sb[2], sb3 = g_sb[3],
          sb4 = g_sb[4], sb5 = g_sb[5], sb6 = g_sb[6];
    float K0 = g_K[0], K1 = g_K[1], K2 = g_K[2], K3 = g_K[3],
          K4 = g_K[4], K5 = g_K[5], K6 = g_K[6];

    // prefetch all 4 step loads (coalesced 128B each) for MLP
    float xr[STEPS];
    #pragma unroll
    for (int c = 0; c < STEPS; c++)
        xr[c] = x[base + 32 * c + lane];

    float4* sbuf = s_w[warp];
    float*  Wp   = weights + (size_t)base * 8;

    #pragma unroll
    for (int c = 0; c < STEPS; c++) {
        float xv = xr[c];
        float ax = fabsf(xv);

        // full-warp amax (non-negative floats compare as uints)
        float amax = __uint_as_float(
            __reduce_max_sync(0xffffffffu, __float_as_uint(ax)));

        // e = clamp(ceil(log2(amax/6)), -127, ..) exactly via exponent bits
        float d = amax * (1.0f / 6.0f);
        int bits = __float_as_int(d);
        int e = (bits >> 23) - 127 + ((bits & 0x7fffff) != 0);
        if (bits < 0x00800000)                     // subnormal/zero d
            e = (bits != 0) ? -126 : -127;         // ceil(log2) of subnormal >= -126... clamp below
        if (e < -127) e = -127;
        float scale, inv_scale;
        if (e >= -126) {
            scale     = __int_as_float((e + 127) << 23);
            inv_scale = __int_as_float((127 - e) << 23);
        } else {                                   // e == -127
            scale     = __int_as_float(1 << 22);   // 2^-127 (subnormal)
            inv_scale = __int_as_float(254 << 23); // 2^127
        }

        if (lane == 0)
            scales[(base >> 5) + c] = (float)(e + 127);

        float xs = xv * inv_scale;                 // exact pow2 scaling
        float xa = fabsf(xs);

        // p_i = 1 / (1 + K_i * exp(-xa/tau))
        float E  = __expf(xa * -10.0f);
        float p0 = __fdividef(1.0f, fmaf(K0, E, 1.0f));
        float p1 = __fdividef(1.0f, fmaf(K1, E, 1.0f));
        float p2 = __fdividef(1.0f, fmaf(K2, E, 1.0f));
        float p3 = __fdividef(1.0f, fmaf(K3, E, 1.0f));
        float p4 = __fdividef(1.0f, fmaf(K4, E, 1.0f));
        float p5 = __fdividef(1.0f, fmaf(K5, E, 1.0f));
        float p6 = __fdividef(1.0f, fmaf(K6, E, 1.0f));

        int ord = (xa > sb0) + (xa > sb1) + (xa > sb2) + (xa > sb3)
                + (xa > sb4) + (xa > sb5) + (xa > sb6);

        // weights (telescoping sum = 1; ref's clip+normalize are no-ops within tol)
        float w0 = 1.0f - p0;
        float w1 = p0 - p1, w2 = p1 - p2, w3 = p2 - p3;
        float w4 = p3 - p4, w5 = p4 - p5, w6 = p5 - p6;
        float w7 = p6;

        float v = __shfl_sync(0xffffffffu, vt_reg, ord);
        y[base + 32 * c + lane]     = ((xs >= 0.0f) ? v : -v) * scale;
        codes[base + 32 * c + lane] = (float)(((xs < 0.0f) ? 8 : 0) | ord);

        // ---- weights writeback for this step: floats [256c, 256c+256) rel warp,
        //      global alignment ≡ 3 mod 4 -> vector region [256c+1, 256c+253).
        float w0n = __shfl_down_sync(0xffffffffu, w0, 1);  // neighbor's w0

        // stage shifted image: slot s covers rel-step floats [4s+1, 4s+5)
        sbuf[swz(2 * lane)]     = make_float4(w1, w2, w3, w4);
        sbuf[swz(2 * lane + 1)] = make_float4(w5, w6, w7, w0n);

        // boundary scalars (outside vector region)
        if (lane == 0)  Wp[256 * c] = w0;
        if (lane == 31) {
            Wp[256 * c + 253] = w5;
            Wp[256 * c + 254] = w6;
            Wp[256 * c + 255] = w7;
        }

        __syncwarp();

        // coalesced flush: 63 float4s cover rel-step [1, 253)
        float4* dst = (float4*)(Wp + 256 * c + 1);
        dst[lane] = sbuf[swz(lane)];
        if (lane < 31)
            dst[32 + lane] = sbuf[swz(32 + lane)];

        __syncwarp();   // protect sbuf reuse next step
    }
}

extern "C" void kernel_launch(void* const* d_in, const int* in_sizes, int n_in,
                              void* d_out, int out_size) {
    const float* x      = (const float*)d_in[0];
    const float* delta  = (const float*)d_in[1];
    const float* bounds = (const float*)d_in[2];
    const float* vt     = (const float*)d_in[3];

    int N = in_sizes[0];
    int n_blocks = N / 32;

    float* out     = (float*)d_out;
    float* y       = out;
    float* codes   = out + (size_t)N;
    float* scales  = out + 2 * (size_t)N;
    float* sb_out  = scales + n_blocks;
    float* weights = sb_out + 7;

    prep_kernel<<<1, 32>>>(delta, bounds, sb_out);

    int elems_per_cta = 32 * STEPS * WARPS_PER_CTA;
    int ctas = (N + elems_per_cta - 1) / elems_per_cta;
    fp4_main<<<ctas, 32 * WARPS_PER_CTA>>>(x, vt, y, codes, scales, weights, N);
}

// round 4
// speedup vs baseline: 1.1174x; 1.1174x over previous
#include <cuda_runtime.h>
#include <cstdint>

// FP4RoundingPerturb — output layout (float32, flattened concat):
//   [0,      N)           y
//   [N,      2N)          codes (as float)
//   [2N,     2N+B)        scales (e8m0+127 as float), B=N/32
//   [2N+B,   2N+B+7)      shifted_bounds
//   [2N+B+7, 2N+B+7+8N)   weights   <-- base float offset ≡ 3 (mod 4)

#define WARPS_PER_CTA 8
#define STEPS 4
// One warp: 128 consecutive elements, 4 steps of 32. In a step, lane L owns
// element 32c+L; the step IS one amax block. Weights are produced output-major
// straight from registers (no smem transpose).

__global__ void __launch_bounds__(32 * WARPS_PER_CTA, 6)
fp4_main(const float* __restrict__ x,
         const float* __restrict__ delta_raw,
         const float* __restrict__ bounds_base,
         const float* __restrict__ values_table,
         float* __restrict__ y,
         float* __restrict__ codes,
         float* __restrict__ scales,
         float* __restrict__ sb_out,
         float* __restrict__ weights,   // float offset ≡ 3 (mod 4)
         int n_elems) {
    const unsigned FULL = 0xffffffffu;
    int tid  = threadIdx.x;
    int warp = tid >> 5;
    int lane = tid & 31;
    int base = (blockIdx.x * WARPS_PER_CTA + warp) * (32 * STEPS);
    if (base >= n_elems) return;

    // ---- per-warp constants (prep fused): sb_i, K_i = exp(sb_i/tau) ----
    int   li     = lane & 7;
    float shift  = 0.5f * tanhf(delta_raw[0]);
    float sb_own = bounds_base[(li < 7) ? li : 6] + shift;
    float K_own  = __expf(sb_own * 10.0f);
    float vt_own = values_table[li];

    if (blockIdx.x == 0 && tid < 7) sb_out[tid] = sb_own;

    float sb0 = __shfl_sync(FULL, sb_own, 0), sb1 = __shfl_sync(FULL, sb_own, 1),
          sb2 = __shfl_sync(FULL, sb_own, 2), sb3 = __shfl_sync(FULL, sb_own, 3),
          sb4 = __shfl_sync(FULL, sb_own, 4), sb5 = __shfl_sync(FULL, sb_own, 5),
          sb6 = __shfl_sync(FULL, sb_own, 6);
    float K0 = __shfl_sync(FULL, K_own, 0), K1 = __shfl_sync(FULL, K_own, 1),
          K2 = __shfl_sync(FULL, K_own, 2), K3 = __shfl_sync(FULL, K_own, 3),
          K4 = __shfl_sync(FULL, K_own, 4), K5 = __shfl_sync(FULL, K_own, 5),
          K6 = __shfl_sync(FULL, K_own, 6);

    // hoisted per-lane slot-parity constant selection (parity = lane&1)
    bool  odd = lane & 1;
    float KA0 = odd ? K4 : K0;
    float KA1 = odd ? K5 : K1;
    float KA2 = odd ? K6 : K2;
    float KA3 = odd ? K0 : K3;

    // prefetch the 4 coalesced step loads
    const float* xp = x + base + lane;
    float xr[STEPS];
    #pragma unroll
    for (int c = 0; c < STEPS; c++) xr[c] = xp[32 * c];

    float* Wg = weights + (size_t)base * 8;   // rel float 0 of this warp tile
    float  E[STEPS];

    // ================= Phase A: element-major =================
    #pragma unroll
    for (int c = 0; c < STEPS; c++) {
        float xv = xr[c];
        float ax = fabsf(xv);
        float amax = __uint_as_float(
            __reduce_max_sync(FULL, __float_as_uint(ax)));

        // e = clamp(ceil(log2(amax/6)), -127, ..) exact via exponent bits
        float d = amax * (1.0f / 6.0f);
        int bits = __float_as_int(d);
        int e = (bits >> 23) - 127 + ((bits & 0x7fffff) != 0);
        if (bits < 0x00800000)                       // subnormal / zero d
            e = (bits > 0x00400000) ? -126 : -127;   // 2^-127 boundary
        bool deep = (e == -127);
        float scale     = deep ? __int_as_float(1 << 22)     // 2^-127 subnormal
                               : __int_as_float((e + 127) << 23);
        float inv_scale = deep ? __int_as_float(254 << 23)   // 2^127
                               : __int_as_float((127 - e) << 23);

        if (lane == 0)
            scales[(base >> 5) + c] = (float)(e + 127);

        float xs = xv * inv_scale;                   // exact pow2 scaling
        float xa = fabsf(xs);
        float Ec = __expf(xa * -10.0f);              // FMUL + MUFU.EX2
        E[c] = Ec;

        int ord = (xa > sb0) + (xa > sb1) + (xa > sb2) + (xa > sb3)
                + (xa > sb4) + (xa > sb5) + (xa > sb6);

        float v = __shfl_sync(FULL, vt_own, ord);
        __stcs(&y[base + 32 * c + lane], copysignf(v * scale, xs));
        __stcs(&codes[base + 32 * c + lane],
               (float)(((xs < 0.0f) ? 8 : 0) | ord));

        // boundary scalars of this step's weight region (outside float4 zone)
        if (lane == 0) {
            float p0 = __fdividef(1.0f, fmaf(K0, Ec, 1.0f));
            __stcs(&Wg[256 * c], 1.0f - p0);
        }
        if (lane == 31) {
            float p4 = __fdividef(1.0f, fmaf(K4, Ec, 1.0f));
            float p5 = __fdividef(1.0f, fmaf(K5, Ec, 1.0f));
            float p6 = __fdividef(1.0f, fmaf(K6, Ec, 1.0f));
            __stcs(&Wg[256 * c + 253], p4 - p5);
            __stcs(&Wg[256 * c + 254], p5 - p6);
            __stcs(&Wg[256 * c + 255], p6);
        }
    }

    // ================= Phase B: output-major weights =================
    // Step region rel floats [256c, 256c+256); vector zone [256c+1, 256c+253)
    // = 63 float4 slots. Slot s covers element m=s>>1:
    //   even s: w1..w4 = p0-p1, p1-p2, p2-p3, p3-p4        (all from E_m)
    //   odd  s: w5,w6,w7 of m = p4-p5, p5-p6, p6; w0 of m+1 = 1-p0(E_{m+1})
    #pragma unroll
    for (int c = 0; c < STEPS; c++) {
        float Ec = E[c];
        #pragma unroll
        for (int j = 0; j < 2; j++) {
            int s  = 32 * j + lane;          // parity(s) == parity(lane)
            int mm = s >> 1;
            float Ea = __shfl_sync(FULL, Ec, mm);
            float Eb = __shfl_sync(FULL, Ec, (mm + 1) & 31);  // unused when even
            float E3 = odd ? Eb : Ea;

            float q0 = __fdividef(1.0f, fmaf(KA0, Ea, 1.0f));
            float q1 = __fdividef(1.0f, fmaf(KA1, Ea, 1.0f));
            float q2 = __fdividef(1.0f, fmaf(KA2, Ea, 1.0f));
            float q3 = __fdividef(1.0f, fmaf(KA3, E3, 1.0f));
            float q4 = __fdividef(1.0f, fmaf(K4,  Ea, 1.0f)); // even only

            float o0 = q0 - q1;
            float o1 = q1 - q2;
            float o2 = odd ? q2 : (q2 - q3);
            float o3 = odd ? (1.0f - q3) : (q3 - q4);

            if (j == 0 || lane < 31)
                __stcs((float4*)(Wg + 256 * c + 4 * s + 1),
                       make_float4(o0, o1, o2, o3));
        }
    }
}

extern "C" void kernel_launch(void* const* d_in, const int* in_sizes, int n_in,
                              void* d_out, int out_size) {
    const float* x      = (const float*)d_in[0];
    const float* delta  = (const float*)d_in[1];
    const float* bounds = (const float*)d_in[2];
    const float* vt     = (const float*)d_in[3];

    int N = in_sizes[0];
    int n_blocks = N / 32;

    float* out     = (float*)d_out;
    float* y       = out;
    float* codes   = out + (size_t)N;
    float* scales  = out + 2 * (size_t)N;
    float* sb_out  = scales + n_blocks;
    float* weights = sb_out + 7;

    int elems_per_cta = 32 * STEPS * WARPS_PER_CTA;
    int ctas = (N + elems_per_cta - 1) / elems_per_cta;
    fp4_main<<<ctas, 32 * WARPS_PER_CTA>>>(x, delta, bounds, vt,
                                           y, codes, scales, sb_out, weights, N);
}